// round 14
// baseline (speedup 1.0000x reference)
#include <cuda_runtime.h>
#include <cuda_fp16.h>
#include <cstdint>

typedef unsigned long long u64;

#define NCH 1563
#define OFF_WD 230600ULL
#define OFF_TH 25830600ULL

__device__ float g_part1[3 * 8 * 100 * 256];
__device__ float g_raw[2 * 3 * 100 * 256];
__device__ float g_part[512 * NCH];
// theta (fp16) in mma-fragment layout: [l][m-tile 16][k-step 7][lane 32] = uint4
__device__ uint4 g_fragH4[2 * 16 * 7 * 32];

__device__ __forceinline__ u64 pack2(float lo, float hi) {
    u64 r; asm("mov.b64 %0, {%1, %2};" : "=l"(r) : "f"(lo), "f"(hi)); return r;
}
__device__ __forceinline__ void unpack2(u64 v, float& lo, float& hi) {
    asm("mov.b64 {%0, %1}, %2;" : "=f"(lo), "=f"(hi) : "l"(v));
}
__device__ __forceinline__ u64 ffma2(u64 a, u64 b, u64 c) {
    u64 d; asm("fma.rn.f32x2 %0, %1, %2, %3;" : "=l"(d) : "l"(a), "l"(b), "l"(c)); return d;
}
__device__ __forceinline__ float softplus_f(float x) {
    return fmaxf(x, 0.0f) + log1pf(expf(-fabsf(x)));
}
__device__ __forceinline__ float erfinv_f(float x) {
    float w = -log1pf(-x * x), p;
    if (w < 5.0f) {
        w -= 2.5f;
        p = 2.81022636e-08f;
        p = fmaf(p, w, 3.43273939e-07f);  p = fmaf(p, w, -3.5233877e-06f);
        p = fmaf(p, w, -4.39150654e-06f); p = fmaf(p, w, 0.00021858087f);
        p = fmaf(p, w, -0.00125372503f);  p = fmaf(p, w, -0.00417768164f);
        p = fmaf(p, w, 0.246640727f);     p = fmaf(p, w, 1.50140941f);
    } else {
        w = sqrtf(w) - 3.0f;
        p = -0.000200214257f;
        p = fmaf(p, w, 0.000100950558f);  p = fmaf(p, w, 0.00134934322f);
        p = fmaf(p, w, -0.00367342844f);  p = fmaf(p, w, 0.00573950773f);
        p = fmaf(p, w, -0.0076224613f);   p = fmaf(p, w, 0.00943887047f);
        p = fmaf(p, w, 1.00167406f);      p = fmaf(p, w, 2.83297682f);
    }
    return p * x;
}
__device__ __forceinline__ void threefry(unsigned k0, unsigned k1, unsigned c0, unsigned c1,
                                         unsigned& o0, unsigned& o1) {
    unsigned ks2 = k0 ^ k1 ^ 0x1BD11BDAu;
    unsigned x0 = c0 + k0, x1 = c1 + k1;
#define TFR(r) { x0 += x1; x1 = __funnelshift_l(x1, x1, r); x1 ^= x0; }
    TFR(13) TFR(15) TFR(26) TFR(6)   x0 += k1;  x1 += ks2 + 1u;
    TFR(17) TFR(29) TFR(16) TFR(24)  x0 += ks2; x1 += k0 + 2u;
    TFR(13) TFR(15) TFR(26) TFR(6)   x0 += k0;  x1 += k1 + 3u;
    TFR(17) TFR(29) TFR(16) TFR(24)  x0 += k1;  x1 += ks2 + 4u;
    TFR(13) TFR(15) TFR(26) TFR(6)   x0 += ks2; x1 += k0 + 5u;
#undef TFR
    o0 = x0; o1 = x1;
}
__device__ __forceinline__ void mma16816(float* c, const uint4& a, unsigned b0, unsigned b1) {
    asm volatile("mma.sync.aligned.m16n8k16.row.col.f32.f16.f16.f32 "
                 "{%0,%1,%2,%3}, {%4,%5,%6,%7}, {%8,%9}, {%0,%1,%2,%3};"
                 : "+f"(c[0]), "+f"(c[1]), "+f"(c[2]), "+f"(c[3])
                 : "r"(a.x), "r"(a.y), "r"(a.z), "r"(a.w), "r"(b0), "r"(b1));
}
__device__ __forceinline__ void ldsm_x4_t(unsigned& r0, unsigned& r1, unsigned& r2, unsigned& r3,
                                          unsigned addr) {
    asm volatile("ldmatrix.sync.aligned.m8n8.x4.trans.shared.b16 {%0,%1,%2,%3}, [%4];"
                 : "=r"(r0), "=r"(r1), "=r"(r2), "=r"(r3) : "r"(addr));
}

// ----------------- layer-1 GEMM, d-split partials. grid (16,8,3), 256 thr -----------------
__global__ __launch_bounds__(256) void kA1(const float* __restrict__ xbert,
                                           const float* __restrict__ ximg,
                                           const float* __restrict__ Wa1,
                                           const float* __restrict__ Wa2,
                                           const float* __restrict__ Wa3) {
    int btile = blockIdx.x, split = blockIdx.y, net = blockIdx.z;
    int nsplit = (net == 2) ? 8 : 3;
    if (split >= nsplit) return;
    const float* X; int rstr; const float* W;
    if (net == 0)      { X = xbert;       rstr = 1536; W = Wa1; }
    else if (net == 1) { X = xbert + 768; rstr = 1536; W = Wa2; }
    else               { X = ximg;        rstr = 2048; W = Wa3; }
    __shared__ float xT[256][20];
    int t = threadIdx.x, b0 = btile * 16, d0 = split * 256;
    for (int idx = t; idx < 16 * 256; idx += 256) {
        int bb = idx >> 8, dd = idx & 255;
        xT[dd][bb] = X[(size_t)(b0 + bb) * rstr + d0 + dd];
    }
    __syncthreads();
    int h = t & 127, bi = t >> 7;
    int hc = h < 100 ? h : 99;
    u64 acc[4];
#pragma unroll
    for (int q = 0; q < 4; q++) acc[q] = 0ull;
#pragma unroll 4
    for (int d = 0; d < 256; d++) {
        float w = W[(size_t)(d0 + d) * 100 + hc];
        u64 ww = pack2(w, w);
        const ulonglong2* xp = reinterpret_cast<const ulonglong2*>(&xT[d][bi * 8]);
#pragma unroll
        for (int q = 0; q < 2; q++) {
            ulonglong2 p = xp[q];
            acc[2 * q]     = ffma2(p.x, ww, acc[2 * q]);
            acc[2 * q + 1] = ffma2(p.y, ww, acc[2 * q + 1]);
        }
    }
    if (h < 100) {
        u64* dst = reinterpret_cast<u64*>(
            &g_part1[(((size_t)net * 8 + split) * 100 + h) * 256 + b0 + bi * 8]);
#pragma unroll
        for (int q = 0; q < 4; q++) dst[q] = acc[q];
    }
}

// ----------------- fused: split-reduce+softplus -> h1, GEMM+softplus -> h2 (smem),
//                   then both head GEMMs -> g_raw. grid (32 btile, 3 net), 256 thr -----------------
__global__ __launch_bounds__(256) void kA34(const float* __restrict__ ba1, const float* __restrict__ ba2,
                                            const float* __restrict__ ba3,
                                            const float* __restrict__ Wh1, const float* __restrict__ Wh2,
                                            const float* __restrict__ Wh3, const float* __restrict__ bh1,
                                            const float* __restrict__ bh2, const float* __restrict__ bh3,
                                            const float* __restrict__ Wm1, const float* __restrict__ Wm2,
                                            const float* __restrict__ Wm3, const float* __restrict__ bm1,
                                            const float* __restrict__ bm2, const float* __restrict__ bm3,
                                            const float* __restrict__ Ws1, const float* __restrict__ Ws2,
                                            const float* __restrict__ Ws3, const float* __restrict__ bs1,
                                            const float* __restrict__ bs2, const float* __restrict__ bs3) {
    int btile = blockIdx.x, net = blockIdx.y;
    int nsplit = (net == 2) ? 8 : 3;
    const float* ba = net == 0 ? ba1 : net == 1 ? ba2 : ba3;
    const float* W  = net == 0 ? Wh1 : net == 1 ? Wh2 : Wh3;
    const float* bh = net == 0 ? bh1 : net == 1 ? bh2 : bh3;
    const float* Wm = net == 0 ? Wm1 : net == 1 ? Wm2 : Wm3;
    const float* bm = net == 0 ? bm1 : net == 1 ? bm2 : bm3;
    const float* Ws = net == 0 ? Ws1 : net == 1 ? Ws2 : Ws3;
    const float* bs = net == 0 ? bs1 : net == 1 ? bs2 : bs3;
    __shared__ float xT[100][12];
    __shared__ float hT[100][12];
    int t = threadIdx.x, b0 = btile * 8;
    for (int idx = t; idx < 800; idx += 256) {
        int k = idx >> 3, bb = idx & 7;
        float s = 0.0f;
        for (int sp = 0; sp < nsplit; sp++)
            s += g_part1[(((size_t)net * 8 + sp) * 100 + k) * 256 + b0 + bb];
        xT[k][bb] = softplus_f(s + ba[k]);
    }
    __syncthreads();
    int h = t & 127, bi = t >> 7;
    int hc = h < 100 ? h : 99;
    {
        u64 acc0 = 0ull, acc1 = 0ull;
#pragma unroll 4
        for (int k = 0; k < 100; k++) {
            float w = W[(size_t)k * 100 + hc];
            u64 ww = pack2(w, w);
            ulonglong2 p = *reinterpret_cast<const ulonglong2*>(&xT[k][bi * 4]);
            acc0 = ffma2(p.x, ww, acc0);
            acc1 = ffma2(p.y, ww, acc1);
        }
        if (h < 100) {
            float bb_ = bh[h];
            float l0, h0, l1, h1;
            unpack2(acc0, l0, h0); unpack2(acc1, l1, h1);
            hT[h][bi * 4 + 0] = softplus_f(l0 + bb_);
            hT[h][bi * 4 + 1] = softplus_f(h0 + bb_);
            hT[h][bi * 4 + 2] = softplus_f(l1 + bb_);
            hT[h][bi * 4 + 3] = softplus_f(h1 + bb_);
        }
    }
    __syncthreads();
    u64 am[2], as_[2];
    am[0] = am[1] = 0ull; as_[0] = as_[1] = 0ull;
#pragma unroll 4
    for (int k = 0; k < 100; k++) {
        float wm = Wm[(size_t)k * 100 + hc];
        float ws = Ws[(size_t)k * 100 + hc];
        u64 wwm = pack2(wm, wm), wws = pack2(ws, ws);
        ulonglong2 p = *reinterpret_cast<const ulonglong2*>(&hT[k][bi * 4]);
        am[0]  = ffma2(p.x, wwm, am[0]);
        am[1]  = ffma2(p.y, wwm, am[1]);
        as_[0] = ffma2(p.x, wws, as_[0]);
        as_[1] = ffma2(p.y, wws, as_[1]);
    }
    if (h < 100) {
        float bmv = bm[h], bsv = bs[h];
        u64* dm = reinterpret_cast<u64*>(&g_raw[((size_t)(0 * 3 + net) * 100 + h) * 256 + b0 + bi * 4]);
        u64* ds = reinterpret_cast<u64*>(&g_raw[((size_t)(1 * 3 + net) * 100 + h) * 256 + b0 + bi * 4]);
#pragma unroll
        for (int q = 0; q < 2; q++) {
            float lo, hi;
            unpack2(am[q], lo, hi);  dm[q] = pack2(lo + bmv, hi + bmv);
            unpack2(as_[q], lo, hi); ds[q] = pack2(lo + bsv, hi + bsv);
        }
    }
}

// ----------------- batchnorm heads -> out. grid (100,3,2), 256 thr -----------------
__global__ __launch_bounds__(256) void kA5(float* __restrict__ out) {
    int k = blockIdx.x, net = blockIdx.y, head = blockIdx.z, b = threadIdx.x;
    int lane = b & 31, warp = b >> 5;
    __shared__ float w8m[8], w8v[8];
    float x = g_raw[((size_t)(head * 3 + net) * 100 + k) * 256 + b];
    float s = x;
#pragma unroll
    for (int o = 16; o > 0; o >>= 1) s += __shfl_xor_sync(0xffffffffu, s, o);
    if (lane == 0) w8m[warp] = s;
    __syncthreads();
    float m = (w8m[0] + w8m[1] + w8m[2] + w8m[3] + w8m[4] + w8m[5] + w8m[6] + w8m[7]) * (1.0f / 256.0f);
    float d = x - m;
    float s2 = d * d;
#pragma unroll
    for (int o = 16; o > 0; o >>= 1) s2 += __shfl_xor_sync(0xffffffffu, s2, o);
    if (lane == 0) w8v[warp] = s2;
    __syncthreads();
    float var = (w8v[0] + w8v[1] + w8v[2] + w8v[3] + w8v[4] + w8v[5] + w8v[6] + w8v[7]) * (1.0f / 256.0f);
    float y = d * rsqrtf(var + 1e-5f);
    size_t base = 200 + (size_t)net * 76800;
    if (head == 0) out[base + (size_t)b * 100 + k] = y;
    else {
        out[base + 51200 + (size_t)b * 100 + k] = y;
        out[base + 25600 + (size_t)b * 100 + k] = __expf(y);
    }
}

// ----------------- RNG + reparam + softmax K + theta frags (fp16). grid (256,3), 128 thr -----------------
__global__ __launch_bounds__(128) void kB(const float* __restrict__ pm, const float* __restrict__ pv,
                                          float* __restrict__ out) {
    int b = blockIdx.x, j = blockIdx.y, t = threadIdx.x;
    if (b == 0 && j == 0 && t < 100) { out[t] = pm[t]; out[100 + t] = pv[t]; }
    __shared__ float red[128];
    float z = 0.0f;
    if (t < 100) {
        unsigned e0, e1, o0, o1;
        threefry(0u, 42u, 0u, (unsigned)j, e0, e1);
        threefry(e0, e1, 0u, (unsigned)(b * 100 + t), o0, o1);
        unsigned bits = o0 ^ o1;
        float f = __uint_as_float((bits >> 9) | 0x3f800000u) - 1.0f;
        float u = fmaxf(fmaf(f, 2.0f, -0.99999994f), -0.99999994f);
        float n = 1.41421356237f * erfinv_f(u);
        size_t base = 200 + (size_t)j * 76800;
        float mu = out[base + (size_t)b * 100 + t];
        float ls = out[base + 51200 + (size_t)b * 100 + t];
        z = mu + n * __expf(0.5f * ls);
    }
    red[t] = (t < 100) ? z : -3.4e38f;
    __syncthreads();
    for (int s = 64; s > 0; s >>= 1) { if (t < s) red[t] = fmaxf(red[t], red[t + s]); __syncthreads(); }
    float mx = red[0];
    __syncthreads();
    float e = (t < 100) ? __expf(z - mx) : 0.0f;
    red[t] = e; __syncthreads();
    for (int s = 64; s > 0; s >>= 1) { if (t < s) red[t] += red[t + s]; __syncthreads(); }
    float sum = red[0];
    float th = (t < 100) ? e / sum : 0.0f;
    if (t < 100) out[OFF_TH + ((size_t)j * 256 + b) * 100 + t] = th;
    if (j < 2 && t < 112) {
        int mt = b >> 4, r = b & 15, ks = t >> 4, kk = t & 15;
        int lane = (r & 7) * 4 + ((kk & 7) >> 1);
        int reg = (r >> 3) + ((kk >> 3) << 1);
        int half = kk & 1;
        size_t fi = ((((size_t)j * 16 + mt) * 7 + ks) * 32 + lane) * 4 + reg;
        reinterpret_cast<__half*>(g_fragH4)[fi * 2 + half] = __float2half_rn(th);
    }
}

// ----------------- decode: TC GEMM (fp16 2-term), 32-v tiles, 3 CTA/SM,
//                   smem-transposed coalesced epilogue. grid (1563, 2), 256 thr -----------------
__global__ __launch_bounds__(256, 3) void kC1(const float* __restrict__ beta,
                                              float* __restrict__ out) {
    int chunk = blockIdx.x, l = blockIdx.y;
    // union pool: staging (BsH 8960B + BsL 8960B = 17920B) vs output tile S (128*40*4 = 20480B)
    __shared__ __align__(16) char pool[20480];
    __half* BsH = reinterpret_cast<__half*>(pool);
    __half* BsL = reinterpret_cast<__half*>(pool + 8960);
    float*  S   = reinterpret_cast<float*>(pool);
    __shared__ float redm[32 * 9];
    __shared__ float ms[32], rss[32];
    int t = threadIdx.x, w = t >> 5, lane = t & 31;
    int vbase = chunk * 32;
    const float* betaL = beta + (size_t)l * 100 * 50000;

    // stage B tile: fp32 -> fp16 hi/lo, layout [k][v] stride 40 halves (80 B)
    for (int idx = t; idx < 800; idx += 256) {
        int k = idx >> 3, v4 = (idx & 7) * 4, vg = vbase + v4;
        float4 val = make_float4(0.f, 0.f, 0.f, 0.f);
        if (vg + 3 < 50000)
            val = *reinterpret_cast<const float4*>(betaL + (size_t)k * 50000 + vg);
        else {
#pragma unroll
            for (int e = 0; e < 4; e++)
                reinterpret_cast<float*>(&val)[e] =
                    (vg + e < 50000) ? betaL[(size_t)k * 50000 + vg + e] : 0.f;
        }
        const float* vv = reinterpret_cast<const float*>(&val);
        __half h[4], lo[4];
#pragma unroll
        for (int e = 0; e < 4; e++) {
            h[e]  = __float2half_rn(vv[e]);
            lo[e] = __float2half_rn(vv[e] - __half2float(h[e]));
        }
        *reinterpret_cast<__half2*>(&BsH[k * 40 + v4])     = __halves2half2(h[0], h[1]);
        *reinterpret_cast<__half2*>(&BsH[k * 40 + v4 + 2]) = __halves2half2(h[2], h[3]);
        *reinterpret_cast<__half2*>(&BsL[k * 40 + v4])     = __halves2half2(lo[0], lo[1]);
        *reinterpret_cast<__half2*>(&BsL[k * 40 + v4 + 2]) = __halves2half2(lo[2], lo[3]);
    }
    __half zb = __float2half_rn(0.f);
    for (int idx = t; idx < 12 * 40; idx += 256) {
        int r = idx / 40, c = idx - r * 40;
        BsH[(100 + r) * 40 + c] = zb;
        BsL[(100 + r) * 40 + c] = zb;
    }
    __syncthreads();

    unsigned sBH = (unsigned)__cvta_generic_to_shared(BsH);
    unsigned sBL = (unsigned)__cvta_generic_to_shared(BsL);

    float acc[2][4][4];
#pragma unroll
    for (int i = 0; i < 2; i++)
#pragma unroll
        for (int nt = 0; nt < 4; nt++)
#pragma unroll
            for (int q = 0; q < 4; q++) acc[i][nt][q] = 0.f;

#pragma unroll
    for (int ks = 0; ks < 7; ks++) {
        uint4 ah0 = g_fragH4[(((size_t)l * 16 + w * 2 + 0) * 7 + ks) * 32 + lane];
        uint4 ah1 = g_fragH4[(((size_t)l * 16 + w * 2 + 1) * 7 + ks) * 32 + lane];
        unsigned rowb = (unsigned)((ks * 16 + (lane & 15)) * 80 + ((lane >> 4) << 4));
#pragma unroll
        for (int np = 0; np < 2; np++) {
            unsigned bh0, bh1, bh2, bh3, bl0, bl1, bl2, bl3;
            ldsm_x4_t(bh0, bh1, bh2, bh3, sBH + rowb + np * 32);
            ldsm_x4_t(bl0, bl1, bl2, bl3, sBL + rowb + np * 32);
            int n0 = np * 2, n1 = np * 2 + 1;
            mma16816(acc[0][n0], ah0, bh0, bh1);
            mma16816(acc[1][n0], ah1, bh0, bh1);
            mma16816(acc[0][n1], ah0, bh2, bh3);
            mma16816(acc[1][n1], ah1, bh2, bh3);
            mma16816(acc[0][n0], ah0, bl0, bl1);
            mma16816(acc[1][n0], ah1, bl0, bl1);
            mma16816(acc[0][n1], ah0, bl2, bl3);
            mma16816(acc[1][n1], ah1, bl2, bl3);
        }
    }

    // BN pass 1: column means
#pragma unroll
    for (int nt = 0; nt < 4; nt++)
#pragma unroll
        for (int h = 0; h < 2; h++) {
            float s = acc[0][nt][h] + acc[0][nt][h + 2] + acc[1][nt][h] + acc[1][nt][h + 2];
            s += __shfl_xor_sync(0xffffffffu, s, 4);
            s += __shfl_xor_sync(0xffffffffu, s, 8);
            s += __shfl_xor_sync(0xffffffffu, s, 16);
            if (lane < 4) redm[(nt * 8 + lane * 2 + h) * 9 + w] = s;
        }
    __syncthreads();
    if (t < 32) {
        float s = 0.f;
#pragma unroll
        for (int ww = 0; ww < 8; ww++) s += redm[t * 9 + ww];
        ms[t] = s * (1.0f / 256.0f);
    }
    __syncthreads();
    // center in place
#pragma unroll
    for (int nt = 0; nt < 4; nt++) {
        float m0 = ms[nt * 8 + (lane & 3) * 2];
        float m1 = ms[nt * 8 + (lane & 3) * 2 + 1];
#pragma unroll
        for (int mt = 0; mt < 2; mt++) {
            acc[mt][nt][0] -= m0; acc[mt][nt][1] -= m1;
            acc[mt][nt][2] -= m0; acc[mt][nt][3] -= m1;
        }
    }
    // BN pass 2: variance of centered values
#pragma unroll
    for (int nt = 0; nt < 4; nt++)
#pragma unroll
        for (int h = 0; h < 2; h++) {
            float s = acc[0][nt][h] * acc[0][nt][h] + acc[0][nt][h + 2] * acc[0][nt][h + 2]
                    + acc[1][nt][h] * acc[1][nt][h] + acc[1][nt][h + 2] * acc[1][nt][h + 2];
            s += __shfl_xor_sync(0xffffffffu, s, 4);
            s += __shfl_xor_sync(0xffffffffu, s, 8);
            s += __shfl_xor_sync(0xffffffffu, s, 16);
            if (lane < 4) redm[(nt * 8 + lane * 2 + h) * 9 + w] = s;
        }
    __syncthreads();
    if (t < 32) {
        float s = 0.f;
#pragma unroll
        for (int ww = 0; ww < 8; ww++) s += redm[t * 9 + ww];
        rss[t] = rsqrtf(s * (1.0f / 256.0f) + 1e-5f);
    }
    __syncthreads();

    // pass 3: per 128-row half — owning warps write exp() into S (transposed),
    // then all threads do coalesced float4 stores + 8-lane rowsum reduction.
#pragma unroll
    for (int half = 0; half < 2; half++) {
        __syncthreads();   // S reuse boundary (also retires staging pool use on first iter)
        if ((w >> 2) == half) {
#pragma unroll
            for (int mt = 0; mt < 2; mt++)
#pragma unroll
                for (int fr = 0; fr < 2; fr++) {
                    int rloc = (w & 3) * 32 + mt * 16 + fr * 8 + (lane >> 2);
#pragma unroll
                    for (int nt = 0; nt < 4; nt++) {
                        int voff = nt * 8 + (lane & 3) * 2;
                        int vg = vbase + voff;
                        float r0 = rss[voff];
                        float r1 = rss[voff + 1];
                        float y0 = (vg     < 50000) ? __expf(acc[mt][nt][fr * 2]     * r0) : 0.f;
                        float y1 = (vg + 1 < 50000) ? __expf(acc[mt][nt][fr * 2 + 1] * r1) : 0.f;
                        *reinterpret_cast<float2*>(&S[rloc * 40 + voff]) = make_float2(y0, y1);
                    }
                }
        }
        __syncthreads();
#pragma unroll
        for (int it = 0; it < 4; it++) {
            int idx = it * 256 + t;
            int rl = idx >> 3, v4 = (idx & 7) * 4;
            float4 v = *reinterpret_cast<const float4*>(&S[rl * 40 + v4]);
            float ps = v.x + v.y + v.z + v.w;
            ps += __shfl_xor_sync(0xffffffffu, ps, 1);
            ps += __shfl_xor_sync(0xffffffffu, ps, 2);
            ps += __shfl_xor_sync(0xffffffffu, ps, 4);
            int row = half * 128 + rl;
            size_t rb = OFF_WD + ((size_t)l * 256 + row) * 50000;
            int vg = vbase + v4;
            if (vg + 3 < 50000) {
                *reinterpret_cast<float4*>(out + rb + vg) = v;
            } else {
                if (vg     < 50000) out[rb + vg]     = v.x;
                if (vg + 1 < 50000) out[rb + vg + 1] = v.y;
                if (vg + 2 < 50000) out[rb + vg + 2] = v.z;
                if (vg + 3 < 50000) out[rb + vg + 3] = v.w;
            }
            if ((t & 7) == 0)
                g_part[((size_t)l * 256 + row) * NCH + chunk] = ps;
        }
    }
}

// ----------------- merged: row-sum reduce + scale. grid (512 rows, 4 seg), 256 thr -----------------
__global__ __launch_bounds__(256) void kC3m(float* __restrict__ out) {
    int row = blockIdx.x, seg = blockIdx.y, t = threadIdx.x;
    __shared__ float red[256];
    float s = 0.f;
    for (int c = t; c < NCH; c += 256) s += g_part[(size_t)row * NCH + c];
    red[t] = s; __syncthreads();
    for (int k = 128; k > 0; k >>= 1) { if (t < k) red[t] += red[t + k]; __syncthreads(); }
    float inv = 1.0f / red[0];
    float4* p = reinterpret_cast<float4*>(out + OFF_WD + (size_t)row * 50000) + seg * 3125;
    for (int i = t; i < 3125; i += 256) {
        float4 v = p[i];
        v.x *= inv; v.y *= inv; v.z *= inv; v.w *= inv;
        p[i] = v;
    }
}

extern "C" void kernel_launch(void* const* d_in, const int* in_sizes, int n_in,
                              void* d_out, int out_size) {
    const float* xbert = (const float*)d_in[1];
    const float* ximg  = (const float*)d_in[2];
    const float* pm    = (const float*)d_in[3];
    const float* pv    = (const float*)d_in[4];
    const float* beta  = (const float*)d_in[5];
    const float *Wa1 = (const float*)d_in[6],  *ba1 = (const float*)d_in[7];
    const float *Wh1 = (const float*)d_in[8],  *bh1 = (const float*)d_in[9];
    const float *Wm1 = (const float*)d_in[10], *bm1 = (const float*)d_in[11];
    const float *Ws1 = (const float*)d_in[12], *bs1 = (const float*)d_in[13];
    const float *Wa2 = (const float*)d_in[14], *ba2 = (const float*)d_in[15];
    const float *Wh2 = (const float*)d_in[16], *bh2 = (const float*)d_in[17];
    const float *Wm2 = (const float*)d_in[18], *bm2 = (const float*)d_in[19];
    const float *Ws2 = (const float*)d_in[20], *bs2 = (const float*)d_in[21];
    const float *Wa3 = (const float*)d_in[22], *ba3 = (const float*)d_in[23];
    const float *Wh3 = (const float*)d_in[24], *bh3 = (const float*)d_in[25];
    const float *Wm3 = (const float*)d_in[26], *bm3 = (const float*)d_in[27];
    const float *Ws3 = (const float*)d_in[28], *bs3 = (const float*)d_in[29];
    float* out = (float*)d_out;

    kA1<<<dim3(16, 8, 3), 256>>>(xbert, ximg, Wa1, Wa2, Wa3);
    kA34<<<dim3(32, 3), 256>>>(ba1, ba2, ba3, Wh1, Wh2, Wh3, bh1, bh2, bh3,
                               Wm1, Wm2, Wm3, bm1, bm2, bm3,
                               Ws1, Ws2, Ws3, bs1, bs2, bs3);
    kA5<<<dim3(100, 3, 2), 256>>>(out);
    kB<<<dim3(256, 3), 128>>>(pm, pv, out);
    kC1<<<dim3(NCH, 2), 256>>>(beta, out);
    kC3m<<<dim3(512, 4), 256>>>(out);
}

// round 15
// speedup vs baseline: 1.0995x; 1.0995x over previous
#include <cuda_runtime.h>
#include <cuda_fp16.h>
#include <cstdint>

typedef unsigned long long u64;

#define NCH 1563
#define OFF_WD 230600ULL
#define OFF_TH 25830600ULL

__device__ float g_part1[3 * 8 * 100 * 256];
__device__ float g_raw[2 * 3 * 100 * 256];
__device__ float g_part[512 * NCH];
// theta (fp16) in mma-fragment layout: [l][m-tile 16][k-step 7][lane 32] = uint4
__device__ uint4 g_fragH4[2 * 16 * 7 * 32];

__device__ __forceinline__ u64 pack2(float lo, float hi) {
    u64 r; asm("mov.b64 %0, {%1, %2};" : "=l"(r) : "f"(lo), "f"(hi)); return r;
}
__device__ __forceinline__ void unpack2(u64 v, float& lo, float& hi) {
    asm("mov.b64 {%0, %1}, %2;" : "=f"(lo), "=f"(hi) : "l"(v));
}
__device__ __forceinline__ u64 ffma2(u64 a, u64 b, u64 c) {
    u64 d; asm("fma.rn.f32x2 %0, %1, %2, %3;" : "=l"(d) : "l"(a), "l"(b), "l"(c)); return d;
}
__device__ __forceinline__ float softplus_f(float x) {
    return fmaxf(x, 0.0f) + log1pf(expf(-fabsf(x)));
}
__device__ __forceinline__ float erfinv_f(float x) {
    float w = -log1pf(-x * x), p;
    if (w < 5.0f) {
        w -= 2.5f;
        p = 2.81022636e-08f;
        p = fmaf(p, w, 3.43273939e-07f);  p = fmaf(p, w, -3.5233877e-06f);
        p = fmaf(p, w, -4.39150654e-06f); p = fmaf(p, w, 0.00021858087f);
        p = fmaf(p, w, -0.00125372503f);  p = fmaf(p, w, -0.00417768164f);
        p = fmaf(p, w, 0.246640727f);     p = fmaf(p, w, 1.50140941f);
    } else {
        w = sqrtf(w) - 3.0f;
        p = -0.000200214257f;
        p = fmaf(p, w, 0.000100950558f);  p = fmaf(p, w, 0.00134934322f);
        p = fmaf(p, w, -0.00367342844f);  p = fmaf(p, w, 0.00573950773f);
        p = fmaf(p, w, -0.0076224613f);   p = fmaf(p, w, 0.00943887047f);
        p = fmaf(p, w, 1.00167406f);      p = fmaf(p, w, 2.83297682f);
    }
    return p * x;
}
__device__ __forceinline__ void threefry(unsigned k0, unsigned k1, unsigned c0, unsigned c1,
                                         unsigned& o0, unsigned& o1) {
    unsigned ks2 = k0 ^ k1 ^ 0x1BD11BDAu;
    unsigned x0 = c0 + k0, x1 = c1 + k1;
#define TFR(r) { x0 += x1; x1 = __funnelshift_l(x1, x1, r); x1 ^= x0; }
    TFR(13) TFR(15) TFR(26) TFR(6)   x0 += k1;  x1 += ks2 + 1u;
    TFR(17) TFR(29) TFR(16) TFR(24)  x0 += ks2; x1 += k0 + 2u;
    TFR(13) TFR(15) TFR(26) TFR(6)   x0 += k0;  x1 += k1 + 3u;
    TFR(17) TFR(29) TFR(16) TFR(24)  x0 += k1;  x1 += ks2 + 4u;
    TFR(13) TFR(15) TFR(26) TFR(6)   x0 += ks2; x1 += k0 + 5u;
#undef TFR
    o0 = x0; o1 = x1;
}
__device__ __forceinline__ void mma16816(float* c, const uint4& a, unsigned b0, unsigned b1) {
    asm volatile("mma.sync.aligned.m16n8k16.row.col.f32.f16.f16.f32 "
                 "{%0,%1,%2,%3}, {%4,%5,%6,%7}, {%8,%9}, {%0,%1,%2,%3};"
                 : "+f"(c[0]), "+f"(c[1]), "+f"(c[2]), "+f"(c[3])
                 : "r"(a.x), "r"(a.y), "r"(a.z), "r"(a.w), "r"(b0), "r"(b1));
}
__device__ __forceinline__ void ldsm_x4_t(unsigned& r0, unsigned& r1, unsigned& r2, unsigned& r3,
                                          unsigned addr) {
    asm volatile("ldmatrix.sync.aligned.m8n8.x4.trans.shared.b16 {%0,%1,%2,%3}, [%4];"
                 : "=r"(r0), "=r"(r1), "=r"(r2), "=r"(r3) : "r"(addr));
}

// ----------------- layer-1 GEMM, d-split partials. grid (16,8,3), 256 thr -----------------
__global__ __launch_bounds__(256) void kA1(const float* __restrict__ xbert,
                                           const float* __restrict__ ximg,
                                           const float* __restrict__ Wa1,
                                           const float* __restrict__ Wa2,
                                           const float* __restrict__ Wa3) {
    int btile = blockIdx.x, split = blockIdx.y, net = blockIdx.z;
    int nsplit = (net == 2) ? 8 : 3;
    if (split >= nsplit) return;
    const float* X; int rstr; const float* W;
    if (net == 0)      { X = xbert;       rstr = 1536; W = Wa1; }
    else if (net == 1) { X = xbert + 768; rstr = 1536; W = Wa2; }
    else               { X = ximg;        rstr = 2048; W = Wa3; }
    __shared__ float xT[256][20];
    int t = threadIdx.x, b0 = btile * 16, d0 = split * 256;
    for (int idx = t; idx < 16 * 256; idx += 256) {
        int bb = idx >> 8, dd = idx & 255;
        xT[dd][bb] = X[(size_t)(b0 + bb) * rstr + d0 + dd];
    }
    __syncthreads();
    int h = t & 127, bi = t >> 7;
    int hc = h < 100 ? h : 99;
    u64 acc[4];
#pragma unroll
    for (int q = 0; q < 4; q++) acc[q] = 0ull;
#pragma unroll 4
    for (int d = 0; d < 256; d++) {
        float w = W[(size_t)(d0 + d) * 100 + hc];
        u64 ww = pack2(w, w);
        const ulonglong2* xp = reinterpret_cast<const ulonglong2*>(&xT[d][bi * 8]);
#pragma unroll
        for (int q = 0; q < 2; q++) {
            ulonglong2 p = xp[q];
            acc[2 * q]     = ffma2(p.x, ww, acc[2 * q]);
            acc[2 * q + 1] = ffma2(p.y, ww, acc[2 * q + 1]);
        }
    }
    if (h < 100) {
        u64* dst = reinterpret_cast<u64*>(
            &g_part1[(((size_t)net * 8 + split) * 100 + h) * 256 + b0 + bi * 8]);
#pragma unroll
        for (int q = 0; q < 4; q++) dst[q] = acc[q];
    }
}

// ----------------- fused: split-reduce+softplus -> h1, GEMM+softplus -> h2 (smem),
//                   then both head GEMMs -> g_raw. grid (32 btile, 3 net), 256 thr -----------------
__global__ __launch_bounds__(256) void kA34(const float* __restrict__ ba1, const float* __restrict__ ba2,
                                            const float* __restrict__ ba3,
                                            const float* __restrict__ Wh1, const float* __restrict__ Wh2,
                                            const float* __restrict__ Wh3, const float* __restrict__ bh1,
                                            const float* __restrict__ bh2, const float* __restrict__ bh3,
                                            const float* __restrict__ Wm1, const float* __restrict__ Wm2,
                                            const float* __restrict__ Wm3, const float* __restrict__ bm1,
                                            const float* __restrict__ bm2, const float* __restrict__ bm3,
                                            const float* __restrict__ Ws1, const float* __restrict__ Ws2,
                                            const float* __restrict__ Ws3, const float* __restrict__ bs1,
                                            const float* __restrict__ bs2, const float* __restrict__ bs3) {
    int btile = blockIdx.x, net = blockIdx.y;
    int nsplit = (net == 2) ? 8 : 3;
    const float* ba = net == 0 ? ba1 : net == 1 ? ba2 : ba3;
    const float* W  = net == 0 ? Wh1 : net == 1 ? Wh2 : Wh3;
    const float* bh = net == 0 ? bh1 : net == 1 ? bh2 : bh3;
    const float* Wm = net == 0 ? Wm1 : net == 1 ? Wm2 : Wm3;
    const float* bm = net == 0 ? bm1 : net == 1 ? bm2 : bm3;
    const float* Ws = net == 0 ? Ws1 : net == 1 ? Ws2 : Ws3;
    const float* bs = net == 0 ? bs1 : net == 1 ? bs2 : bs3;
    __shared__ float xT[100][12];
    __shared__ float hT[100][12];
    int t = threadIdx.x, b0 = btile * 8;
    for (int idx = t; idx < 800; idx += 256) {
        int k = idx >> 3, bb = idx & 7;
        float s = 0.0f;
        for (int sp = 0; sp < nsplit; sp++)
            s += g_part1[(((size_t)net * 8 + sp) * 100 + k) * 256 + b0 + bb];
        xT[k][bb] = softplus_f(s + ba[k]);
    }
    __syncthreads();
    int h = t & 127, bi = t >> 7;
    int hc = h < 100 ? h : 99;
    {
        u64 acc0 = 0ull, acc1 = 0ull;
#pragma unroll 4
        for (int k = 0; k < 100; k++) {
            float w = W[(size_t)k * 100 + hc];
            u64 ww = pack2(w, w);
            ulonglong2 p = *reinterpret_cast<const ulonglong2*>(&xT[k][bi * 4]);
            acc0 = ffma2(p.x, ww, acc0);
            acc1 = ffma2(p.y, ww, acc1);
        }
        if (h < 100) {
            float bb_ = bh[h];
            float l0, h0, l1, h1;
            unpack2(acc0, l0, h0); unpack2(acc1, l1, h1);
            hT[h][bi * 4 + 0] = softplus_f(l0 + bb_);
            hT[h][bi * 4 + 1] = softplus_f(h0 + bb_);
            hT[h][bi * 4 + 2] = softplus_f(l1 + bb_);
            hT[h][bi * 4 + 3] = softplus_f(h1 + bb_);
        }
    }
    __syncthreads();
    u64 am[2], as_[2];
    am[0] = am[1] = 0ull; as_[0] = as_[1] = 0ull;
#pragma unroll 4
    for (int k = 0; k < 100; k++) {
        float wm = Wm[(size_t)k * 100 + hc];
        float ws = Ws[(size_t)k * 100 + hc];
        u64 wwm = pack2(wm, wm), wws = pack2(ws, ws);
        ulonglong2 p = *reinterpret_cast<const ulonglong2*>(&hT[k][bi * 4]);
        am[0]  = ffma2(p.x, wwm, am[0]);
        am[1]  = ffma2(p.y, wwm, am[1]);
        as_[0] = ffma2(p.x, wws, as_[0]);
        as_[1] = ffma2(p.y, wws, as_[1]);
    }
    if (h < 100) {
        float bmv = bm[h], bsv = bs[h];
        u64* dm = reinterpret_cast<u64*>(&g_raw[((size_t)(0 * 3 + net) * 100 + h) * 256 + b0 + bi * 4]);
        u64* ds = reinterpret_cast<u64*>(&g_raw[((size_t)(1 * 3 + net) * 100 + h) * 256 + b0 + bi * 4]);
#pragma unroll
        for (int q = 0; q < 2; q++) {
            float lo, hi;
            unpack2(am[q], lo, hi);  dm[q] = pack2(lo + bmv, hi + bmv);
            unpack2(as_[q], lo, hi); ds[q] = pack2(lo + bsv, hi + bsv);
        }
    }
}

// ----------------- batchnorm heads -> out. grid (100,3,2), 256 thr -----------------
__global__ __launch_bounds__(256) void kA5(float* __restrict__ out) {
    int k = blockIdx.x, net = blockIdx.y, head = blockIdx.z, b = threadIdx.x;
    int lane = b & 31, warp = b >> 5;
    __shared__ float w8m[8], w8v[8];
    float x = g_raw[((size_t)(head * 3 + net) * 100 + k) * 256 + b];
    float s = x;
#pragma unroll
    for (int o = 16; o > 0; o >>= 1) s += __shfl_xor_sync(0xffffffffu, s, o);
    if (lane == 0) w8m[warp] = s;
    __syncthreads();
    float m = (w8m[0] + w8m[1] + w8m[2] + w8m[3] + w8m[4] + w8m[5] + w8m[6] + w8m[7]) * (1.0f / 256.0f);
    float d = x - m;
    float s2 = d * d;
#pragma unroll
    for (int o = 16; o > 0; o >>= 1) s2 += __shfl_xor_sync(0xffffffffu, s2, o);
    if (lane == 0) w8v[warp] = s2;
    __syncthreads();
    float var = (w8v[0] + w8v[1] + w8v[2] + w8v[3] + w8v[4] + w8v[5] + w8v[6] + w8v[7]) * (1.0f / 256.0f);
    float y = d * rsqrtf(var + 1e-5f);
    size_t base = 200 + (size_t)net * 76800;
    if (head == 0) out[base + (size_t)b * 100 + k] = y;
    else {
        out[base + 51200 + (size_t)b * 100 + k] = y;
        out[base + 25600 + (size_t)b * 100 + k] = __expf(y);
    }
}

// ----------------- RNG + reparam + softmax K + theta frags (fp16). grid (256,3), 128 thr -----------------
__global__ __launch_bounds__(128) void kB(const float* __restrict__ pm, const float* __restrict__ pv,
                                          float* __restrict__ out) {
    int b = blockIdx.x, j = blockIdx.y, t = threadIdx.x;
    if (b == 0 && j == 0 && t < 100) { out[t] = pm[t]; out[100 + t] = pv[t]; }
    __shared__ float red[128];
    float z = 0.0f;
    if (t < 100) {
        unsigned e0, e1, o0, o1;
        threefry(0u, 42u, 0u, (unsigned)j, e0, e1);
        threefry(e0, e1, 0u, (unsigned)(b * 100 + t), o0, o1);
        unsigned bits = o0 ^ o1;
        float f = __uint_as_float((bits >> 9) | 0x3f800000u) - 1.0f;
        float u = fmaxf(fmaf(f, 2.0f, -0.99999994f), -0.99999994f);
        float n = 1.41421356237f * erfinv_f(u);
        size_t base = 200 + (size_t)j * 76800;
        float mu = out[base + (size_t)b * 100 + t];
        float ls = out[base + 51200 + (size_t)b * 100 + t];
        z = mu + n * __expf(0.5f * ls);
    }
    red[t] = (t < 100) ? z : -3.4e38f;
    __syncthreads();
    for (int s = 64; s > 0; s >>= 1) { if (t < s) red[t] = fmaxf(red[t], red[t + s]); __syncthreads(); }
    float mx = red[0];
    __syncthreads();
    float e = (t < 100) ? __expf(z - mx) : 0.0f;
    red[t] = e; __syncthreads();
    for (int s = 64; s > 0; s >>= 1) { if (t < s) red[t] += red[t + s]; __syncthreads(); }
    float sum = red[0];
    float th = (t < 100) ? e / sum : 0.0f;
    if (t < 100) out[OFF_TH + ((size_t)j * 256 + b) * 100 + t] = th;
    if (j < 2 && t < 112) {
        int mt = b >> 4, r = b & 15, ks = t >> 4, kk = t & 15;
        int lane = (r & 7) * 4 + ((kk & 7) >> 1);
        int reg = (r >> 3) + ((kk >> 3) << 1);
        int half = kk & 1;
        size_t fi = ((((size_t)j * 16 + mt) * 7 + ks) * 32 + lane) * 4 + reg;
        reinterpret_cast<__half*>(g_fragH4)[fi * 2 + half] = __float2half_rn(th);
    }
}

// ----------------- decode: TC GEMM (fp16 2-term), 32-v tiles, 3 CTA/SM.
//                   beta staged with evict-first loads. grid (1563, 2), 256 thr -----------------
__global__ __launch_bounds__(256, 3) void kC1(const float* __restrict__ beta,
                                              float* __restrict__ out) {
    int chunk = blockIdx.x, l = blockIdx.y;
    __shared__ __half BsH[112 * 40], BsL[112 * 40];
    __shared__ float redm[32 * 9];
    __shared__ float ms[32], rss[32];
    int t = threadIdx.x, w = t >> 5, lane = t & 31;
    int vbase = chunk * 32;
    const float* betaL = beta + (size_t)l * 100 * 50000;

    // stage B tile: fp32 -> fp16 hi/lo, layout [k][v] stride 40 halves (80 B)
    // beta lines are read exactly once -> evict-first, keep L2 for the wd stream
    for (int idx = t; idx < 800; idx += 256) {
        int k = idx >> 3, v4 = (idx & 7) * 4, vg = vbase + v4;
        float4 val = make_float4(0.f, 0.f, 0.f, 0.f);
        if (vg + 3 < 50000)
            val = __ldcs(reinterpret_cast<const float4*>(betaL + (size_t)k * 50000 + vg));
        else {
#pragma unroll
            for (int e = 0; e < 4; e++)
                reinterpret_cast<float*>(&val)[e] =
                    (vg + e < 50000) ? betaL[(size_t)k * 50000 + vg + e] : 0.f;
        }
        const float* vv = reinterpret_cast<const float*>(&val);
        __half h[4], lo[4];
#pragma unroll
        for (int e = 0; e < 4; e++) {
            h[e]  = __float2half_rn(vv[e]);
            lo[e] = __float2half_rn(vv[e] - __half2float(h[e]));
        }
        *reinterpret_cast<__half2*>(&BsH[k * 40 + v4])     = __halves2half2(h[0], h[1]);
        *reinterpret_cast<__half2*>(&BsH[k * 40 + v4 + 2]) = __halves2half2(h[2], h[3]);
        *reinterpret_cast<__half2*>(&BsL[k * 40 + v4])     = __halves2half2(lo[0], lo[1]);
        *reinterpret_cast<__half2*>(&BsL[k * 40 + v4 + 2]) = __halves2half2(lo[2], lo[3]);
    }
    __half zb = __float2half_rn(0.f);
    for (int idx = t; idx < 12 * 40; idx += 256) {
        int r = idx / 40, c = idx - r * 40;
        BsH[(100 + r) * 40 + c] = zb;
        BsL[(100 + r) * 40 + c] = zb;
    }
    __syncthreads();

    unsigned sBH = (unsigned)__cvta_generic_to_shared(BsH);
    unsigned sBL = (unsigned)__cvta_generic_to_shared(BsL);

    float acc[2][4][4];
#pragma unroll
    for (int i = 0; i < 2; i++)
#pragma unroll
        for (int nt = 0; nt < 4; nt++)
#pragma unroll
            for (int q = 0; q < 4; q++) acc[i][nt][q] = 0.f;

#pragma unroll
    for (int ks = 0; ks < 7; ks++) {
        uint4 ah0 = g_fragH4[(((size_t)l * 16 + w * 2 + 0) * 7 + ks) * 32 + lane];
        uint4 ah1 = g_fragH4[(((size_t)l * 16 + w * 2 + 1) * 7 + ks) * 32 + lane];
        unsigned rowb = (unsigned)((ks * 16 + (lane & 15)) * 80 + ((lane >> 4) << 4));
#pragma unroll
        for (int np = 0; np < 2; np++) {
            unsigned bh0, bh1, bh2, bh3, bl0, bl1, bl2, bl3;
            ldsm_x4_t(bh0, bh1, bh2, bh3, sBH + rowb + np * 32);
            ldsm_x4_t(bl0, bl1, bl2, bl3, sBL + rowb + np * 32);
            int n0 = np * 2, n1 = np * 2 + 1;
            mma16816(acc[0][n0], ah0, bh0, bh1);
            mma16816(acc[1][n0], ah1, bh0, bh1);
            mma16816(acc[0][n1], ah0, bh2, bh3);
            mma16816(acc[1][n1], ah1, bh2, bh3);
            mma16816(acc[0][n0], ah0, bl0, bl1);
            mma16816(acc[1][n0], ah1, bl0, bl1);
            mma16816(acc[0][n1], ah0, bl2, bl3);
            mma16816(acc[1][n1], ah1, bl2, bl3);
        }
    }

    // BN pass 1: column means
#pragma unroll
    for (int nt = 0; nt < 4; nt++)
#pragma unroll
        for (int h = 0; h < 2; h++) {
            float s = acc[0][nt][h] + acc[0][nt][h + 2] + acc[1][nt][h] + acc[1][nt][h + 2];
            s += __shfl_xor_sync(0xffffffffu, s, 4);
            s += __shfl_xor_sync(0xffffffffu, s, 8);
            s += __shfl_xor_sync(0xffffffffu, s, 16);
            if (lane < 4) redm[(nt * 8 + lane * 2 + h) * 9 + w] = s;
        }
    __syncthreads();
    if (t < 32) {
        float s = 0.f;
#pragma unroll
        for (int ww = 0; ww < 8; ww++) s += redm[t * 9 + ww];
        ms[t] = s * (1.0f / 256.0f);
    }
    __syncthreads();
    // center in place
#pragma unroll
    for (int nt = 0; nt < 4; nt++) {
        float m0 = ms[nt * 8 + (lane & 3) * 2];
        float m1 = ms[nt * 8 + (lane & 3) * 2 + 1];
#pragma unroll
        for (int mt = 0; mt < 2; mt++) {
            acc[mt][nt][0] -= m0; acc[mt][nt][1] -= m1;
            acc[mt][nt][2] -= m0; acc[mt][nt][3] -= m1;
        }
    }
    // BN pass 2: variance of centered values
#pragma unroll
    for (int nt = 0; nt < 4; nt++)
#pragma unroll
        for (int h = 0; h < 2; h++) {
            float s = acc[0][nt][h] * acc[0][nt][h] + acc[0][nt][h + 2] * acc[0][nt][h + 2]
                    + acc[1][nt][h] * acc[1][nt][h] + acc[1][nt][h + 2] * acc[1][nt][h + 2];
            s += __shfl_xor_sync(0xffffffffu, s, 4);
            s += __shfl_xor_sync(0xffffffffu, s, 8);
            s += __shfl_xor_sync(0xffffffffu, s, 16);
            if (lane < 4) redm[(nt * 8 + lane * 2 + h) * 9 + w] = s;
        }
    __syncthreads();
    if (t < 32) {
        float s = 0.f;
#pragma unroll
        for (int ww = 0; ww < 8; ww++) s += redm[t * 9 + ww];
        rss[t] = rsqrtf(s * (1.0f / 256.0f) + 1e-5f);
    }
    __syncthreads();

    // pass 3: scale, exp, store (normal policy -> stays in L2 for kC3m), row partials
    float rowsum[4] = {0.f, 0.f, 0.f, 0.f};
#pragma unroll
    for (int mt = 0; mt < 2; mt++)
#pragma unroll
        for (int fr = 0; fr < 2; fr++) {
            int row = w * 32 + mt * 16 + fr * 8 + (lane >> 2);
            size_t rb = OFF_WD + ((size_t)l * 256 + row) * 50000;
#pragma unroll
            for (int nt = 0; nt < 4; nt++) {
                int v0 = vbase + nt * 8 + (lane & 3) * 2;
                if (v0 < 50000) {
                    float r0 = rss[nt * 8 + (lane & 3) * 2];
                    float r1 = rss[nt * 8 + (lane & 3) * 2 + 1];
                    float y0 = __expf(acc[mt][nt][fr * 2]     * r0);
                    float y1 = __expf(acc[mt][nt][fr * 2 + 1] * r1);
                    rowsum[mt * 2 + fr] += y0 + y1;
                    float2 yy; yy.x = y0; yy.y = y1;
                    *reinterpret_cast<float2*>(out + rb + v0) = yy;
                }
            }
        }
#pragma unroll
    for (int i = 0; i < 4; i++) {
        float r = rowsum[i];
        r += __shfl_xor_sync(0xffffffffu, r, 1);
        r += __shfl_xor_sync(0xffffffffu, r, 2);
        if ((lane & 3) == 0) {
            int row = w * 32 + (i >> 1) * 16 + (i & 1) * 8 + (lane >> 2);
            g_part[((size_t)l * 256 + row) * NCH + chunk] = r;
        }
    }
}

// ----------------- merged: row-sum reduce + scale. grid (512 rows, 4 seg), 256 thr -----------------
__global__ __launch_bounds__(256) void kC3m(float* __restrict__ out) {
    int row = blockIdx.x, seg = blockIdx.y, t = threadIdx.x;
    __shared__ float red[256];
    float s = 0.f;
    for (int c = t; c < NCH; c += 256) s += g_part[(size_t)row * NCH + c];
    red[t] = s; __syncthreads();
    for (int k = 128; k > 0; k >>= 1) { if (t < k) red[t] += red[t + k]; __syncthreads(); }
    float inv = 1.0f / red[0];
    float4* p = reinterpret_cast<float4*>(out + OFF_WD + (size_t)row * 50000) + seg * 3125;
    for (int i = t; i < 3125; i += 256) {
        float4 v = p[i];              // hope: L2 hit from kC1's write
        v.x *= inv; v.y *= inv; v.z *= inv; v.w *= inv;
        __stcs(p + i, v);             // final write, never re-read -> evict-first
    }
}

extern "C" void kernel_launch(void* const* d_in, const int* in_sizes, int n_in,
                              void* d_out, int out_size) {
    const float* xbert = (const float*)d_in[1];
    const float* ximg  = (const float*)d_in[2];
    const float* pm    = (const float*)d_in[3];
    const float* pv    = (const float*)d_in[4];
    const float* beta  = (const float*)d_in[5];
    const float *Wa1 = (const float*)d_in[6],  *ba1 = (const float*)d_in[7];
    const float *Wh1 = (const float*)d_in[8],  *bh1 = (const float*)d_in[9];
    const float *Wm1 = (const float*)d_in[10], *bm1 = (const float*)d_in[11];
    const float *Ws1 = (const float*)d_in[12], *bs1 = (const float*)d_in[13];
    const float *Wa2 = (const float*)d_in[14], *ba2 = (const float*)d_in[15];
    const float *Wh2 = (const float*)d_in[16], *bh2 = (const float*)d_in[17];
    const float *Wm2 = (const float*)d_in[18], *bm2 = (const float*)d_in[19];
    const float *Ws2 = (const float*)d_in[20], *bs2 = (const float*)d_in[21];
    const float *Wa3 = (const float*)d_in[22], *ba3 = (const float*)d_in[23];
    const float *Wh3 = (const float*)d_in[24], *bh3 = (const float*)d_in[25];
    const float *Wm3 = (const float*)d_in[26], *bm3 = (const float*)d_in[27];
    const float *Ws3 = (const float*)d_in[28], *bs3 = (const float*)d_in[29];
    float* out = (float*)d_out;

    kA1<<<dim3(16, 8, 3), 256>>>(xbert, ximg, Wa1, Wa2, Wa3);
    kA34<<<dim3(32, 3), 256>>>(ba1, ba2, ba3, Wh1, Wh2, Wh3, bh1, bh2, bh3,
                               Wm1, Wm2, Wm3, bm1, bm2, bm3,
                               Ws1, Ws2, Ws3, bs1, bs2, bs3);
    kA5<<<dim3(100, 3, 2), 256>>>(out);
    kB<<<dim3(256, 3), 128>>>(pm, pv, out);
    kC1<<<dim3(NCH, 2), 256>>>(beta, out);
    kC3m<<<dim3(512, 4), 256>>>(out);
}